// round 17
// baseline (speedup 1.0000x reference)
#include <cuda_runtime.h>
#include <cuda_bf16.h>
#include <cuda_fp16.h>
#include <mma.h>

using namespace nvcuda;

#define NN   50000
#define EE   800000
#define GG   256
#define HH   128
#define NHID 256
#define NOUT 128

// ---------------- scratch (static device globals; no allocations) ----------------
__device__ __half g_h0[NN * HH];     // GEMM1 output (x @ W0)
__device__ __half g_h1[NN * HH];     // GCN layer output
__device__ __half g_h2[NN * HH];     // GIN1 output
__device__ int   g_perm[EE];
__device__ int   g_deg[NN];
__device__ int   g_offs[NN + 1];
__device__ int   g_cursor[NN];
__device__ float g_dinv[NN];
__device__ int   g_batch[NN];
__device__ float g_pool[GG * HH];
__device__ float g_cnt[GG];
__device__ int   g_is64;
__device__ int   g_bsum[64];
// W0 bf16 hi/lo images (3-product GEMM1); Wg1/Wg2 fp16 hi/lo images (2-product GIN)
__device__ __nv_bfloat16 g_Wbh[16384];
__device__ __nv_bfloat16 g_Wbl[16384];
__device__ __half        g_Wfh[2 * 16384];
__device__ __half        g_Wfl[2 * 16384];

__device__ __forceinline__ float4 f4zero() { return make_float4(0.f, 0.f, 0.f, 0.f); }

// 4 halves (uint2) <-> float4
__device__ __forceinline__ float4 h2f4(uint2 v) {
    __half2 a = *(__half2*)&v.x, b = *(__half2*)&v.y;
    float2 fa = __half22float2(a), fb = __half22float2(b);
    return make_float4(fa.x, fa.y, fb.x, fb.y);
}
__device__ __forceinline__ uint2 f42h(float4 o) {
    __half2 a = __float22half2_rn(make_float2(o.x, o.y));
    __half2 b = __float22half2_rn(make_float2(o.z, o.w));
    uint2 r; r.x = *(unsigned*)&a; r.y = *(unsigned*)&b; return r;
}

// split fp32 -> (hi, lo) bf16 packed pairs
__device__ __forceinline__ void split4(float4 v, uint2& hi, uint2& lo) {
    __nv_bfloat16 bx = __float2bfloat16(v.x), by = __float2bfloat16(v.y);
    __nv_bfloat16 bz = __float2bfloat16(v.z), bw = __float2bfloat16(v.w);
    hi.x = (unsigned)__bfloat16_as_ushort(bx) | ((unsigned)__bfloat16_as_ushort(by) << 16);
    hi.y = (unsigned)__bfloat16_as_ushort(bz) | ((unsigned)__bfloat16_as_ushort(bw) << 16);
    __nv_bfloat16 lx = __float2bfloat16(v.x - __bfloat162float(bx));
    __nv_bfloat16 ly = __float2bfloat16(v.y - __bfloat162float(by));
    __nv_bfloat16 lz = __float2bfloat16(v.z - __bfloat162float(bz));
    __nv_bfloat16 lw = __float2bfloat16(v.w - __bfloat162float(bw));
    lo.x = (unsigned)__bfloat16_as_ushort(lx) | ((unsigned)__bfloat16_as_ushort(ly) << 16);
    lo.y = (unsigned)__bfloat16_as_ushort(lz) | ((unsigned)__bfloat16_as_ushort(lw) << 16);
}

// ---------------- setup: zero + dtype detect + weight split prep -----------------
__global__ void k_setup(const unsigned int* __restrict__ w,
                        const float* __restrict__ W0, const float* __restrict__ Wg1,
                        const float* __restrict__ Wg2) {
    int i = blockIdx.x * blockDim.x + threadIdx.x;
    if (i < NN) g_deg[i] = 0;
    if (i < GG * HH) g_pool[i] = 0.f;
    if (i < GG) g_cnt[i] = 0.f;
    if (blockIdx.x == 0) {
        __shared__ int nz;
        if (threadIdx.x == 0) nz = 0;
        __syncthreads();
        for (int t = threadIdx.x; t < 2048; t += blockDim.x)
            if (w[2 * t + 1] != 0u) nz = 1;   // benign race
        __syncthreads();
        if (threadIdx.x == 0) g_is64 = (nz == 0) ? 1 : 0;
    }
    int p = i - 50176;
    if (p >= 0 && p < 16384) {            // W0 -> bf16 hi/lo
        float v = W0[p];
        __nv_bfloat16 h = __float2bfloat16(v);
        g_Wbh[p] = h;
        g_Wbl[p] = __float2bfloat16(v - __bfloat162float(h));
    } else if (p >= 16384 && p < 3 * 16384) {   // Wg1/Wg2 -> fp16 hi/lo
        int q = p - 16384;
        const float* Ws = (q < 16384) ? Wg1 : Wg2;
        float v = Ws[q & 16383];
        __half h = __float2half(v);
        g_Wfh[q] = h;
        g_Wfl[q] = __float2half(v - __half2float(h));
    }
}

// Degree count + batch convert + per-graph node count.
__global__ void k_count(const void* __restrict__ ei, const void* __restrict__ batch) {
    int i = blockIdx.x * blockDim.x + threadIdx.x;
    int is64 = g_is64;
    if (i < EE) {
        int d = is64 ? (int)((const long long*)ei)[EE + i] : ((const int*)ei)[EE + i];
        atomicAdd(&g_deg[d], 1);
    }
    if (i < NN) {
        int b = is64 ? (int)((const long long*)batch)[i] : ((const int*)batch)[i];
        g_batch[i] = b;
        atomicAdd(&g_cnt[b], 1.f);
    }
}

// ---------------- parallel 3-phase scan + dinv ------------------------------------
__global__ void k_scanA() {
    __shared__ int sh[1024];
    int b = blockIdx.x, t = threadIdx.x, i = b * 1024 + t;
    int v = (i < NN) ? g_deg[i] : 0;
    sh[t] = v;
    __syncthreads();
    for (int d = 1; d < 1024; d <<= 1) {
        int u = (t >= d) ? sh[t - d] : 0;
        __syncthreads();
        sh[t] += u;
        __syncthreads();
    }
    if (i < NN) {
        g_offs[i + 1] = sh[t];
        g_dinv[i] = rsqrtf((float)(v + 1));
    }
    if (t == 1023) g_bsum[b] = sh[1023];
}

__global__ void k_scanB() {
    int run = 0;
    for (int b = 0; b < 49; b++) { int s = g_bsum[b]; g_bsum[b] = run; run += s; }
    g_offs[0] = 0;
}

__global__ void k_scanC() {
    int b = blockIdx.x, t = threadIdx.x, i = b * 1024 + t;
    if (i < NN) {
        int off = g_offs[i + 1] + g_bsum[b];
        g_offs[i + 1] = off;
        g_cursor[i] = off - g_deg[i];
    }
}

__global__ void k_fill(const void* __restrict__ ei) {
    int i = blockIdx.x * blockDim.x + threadIdx.x;
    if (i < EE) {
        int s, d;
        if (g_is64) {
            const long long* p = (const long long*)ei;
            s = (int)p[i]; d = (int)p[EE + i];
        } else {
            const int* p = (const int*)ei;
            s = p[i]; d = p[EE + i];
        }
        int slot = atomicAdd(&g_cursor[d], 1);
        g_perm[slot] = s;
    }
}

// sum 16 gathered half rows into acc (16 loads in flight)
#define GATHER16(hh, base_j)                                                    \
    do {                                                                        \
        int ix[16];                                                             \
        _Pragma("unroll")                                                       \
        for (int t = 0; t < 16; t++) ix[t] = g_perm[(base_j) + t];              \
        uint2 rr[16];                                                           \
        _Pragma("unroll")                                                       \
        for (int t = 0; t < 16; t++) rr[t] = hh[ix[t] * 32 + lane];             \
        _Pragma("unroll")                                                       \
        for (int t = 0; t < 16; t += 4) {                                       \
            float4 uA = h2f4(rr[t]), uB = h2f4(rr[t + 1]);                      \
            float4 uC = h2f4(rr[t + 2]), uD = h2f4(rr[t + 3]);                  \
            acc.x += (uA.x + uB.x) + (uC.x + uD.x);                             \
            acc.y += (uA.y + uB.y) + (uC.y + uD.y);                             \
            acc.z += (uA.z + uB.z) + (uC.z + uD.z);                             \
            acc.w += (uA.w + uB.w) + (uC.w + uD.w);                             \
        }                                                                       \
    } while (0)

#define AST 136     // A smem stride (elements)
#define CST 132     // epilogue smem stride (floats)

// ---------------- GEMM1: C_h16[M,128] = (x_f32 @ W0), bf16 3-product -------------
__global__ void __launch_bounds__(256)
k_wmma0(const float* __restrict__ A, __half* __restrict__ Cout, int M) {
    __shared__ __align__(16) char sm[64 * AST * 2 * 2];   // 34816 B
    __nv_bfloat16* sa_hi = (__nv_bfloat16*)sm;
    __nv_bfloat16* sa_lo = (__nv_bfloat16*)(sm + 64 * AST * 2);
    int tid = threadIdx.x, wid = tid >> 5;
    int m0 = blockIdx.x * 64;

    const float4* A4 = (const float4*)A;
#pragma unroll
    for (int i = 0; i < 8; i++) {
        int idx = tid + i * 256;
        int r = idx >> 5, q = idx & 31;
        float4 v = (m0 + r < M) ? __ldg(&A4[(m0 + r) * 32 + q]) : f4zero();
        uint2 hi, lo;
        split4(v, hi, lo);
        *(uint2*)(sa_hi + r * AST + q * 4) = hi;
        *(uint2*)(sa_lo + r * AST + q * 4) = lo;
    }
    __syncthreads();

    wmma::fragment<wmma::accumulator, 16, 16, 16, float> facc[4];
#pragma unroll
    for (int r = 0; r < 4; r++) wmma::fill_fragment(facc[r], 0.f);

    const __nv_bfloat16* Bh = g_Wbh + wid * 16;
    const __nv_bfloat16* Bl = g_Wbl + wid * 16;

#pragma unroll 1
    for (int k = 0; k < 8; k++) {
        wmma::fragment<wmma::matrix_b, 16, 16, 16, __nv_bfloat16, wmma::row_major> bh, bl;
        wmma::load_matrix_sync(bh, Bh + (k * 16) * 128, 128);
        wmma::load_matrix_sync(bl, Bl + (k * 16) * 128, 128);
#pragma unroll
        for (int r = 0; r < 4; r++) {
            wmma::fragment<wmma::matrix_a, 16, 16, 16, __nv_bfloat16, wmma::row_major> ah, al;
            wmma::load_matrix_sync(ah, sa_hi + (r * 16) * AST + k * 16, AST);
            wmma::load_matrix_sync(al, sa_lo + (r * 16) * AST + k * 16, AST);
            wmma::mma_sync(facc[r], ah, bh, facc[r]);
            wmma::mma_sync(facc[r], ah, bl, facc[r]);
            wmma::mma_sync(facc[r], al, bh, facc[r]);
        }
    }

    __syncthreads();
    float* cs = (float*)sm;
#pragma unroll
    for (int r = 0; r < 4; r++)
        wmma::store_matrix_sync(cs + (r * 16) * CST + wid * 16, facc[r], CST,
                                wmma::mem_row_major);
    __syncthreads();

#pragma unroll
    for (int i = 0; i < 8; i++) {
        int idx = tid + i * 256;
        int r = idx >> 5, q = idx & 31;
        int grow = m0 + r;
        if (grow < M)
            ((uint2*)Cout)[grow * 32 + q] = f42h(*(float4*)(cs + r * CST + q * 4));
    }
}

// ---------------- fused GIN: gather(fp16) -> fp16 A x fp16-split W (2 products) ---
// mode 1: write relu(C+bias) as half plane; mode 2: pool relu(C+bias) into g_pool.
__global__ void __launch_bounds__(256)
k_wmma_gin(const __half* __restrict__ Ain, int widx,
           const float* __restrict__ bias,
           __half* __restrict__ Cout, int M, int mode) {
    __shared__ __align__(16) char sm[64 * AST * 2];   // 17408 B (A plane / epi chunk)
    __shared__ int sbat[64];
    __half* sa = (__half*)sm;
    int tid = threadIdx.x, wid = tid >> 5, lane = tid & 31;
    int m0 = blockIdx.x * 64;

    // ---- gather fill: A row = h[node] + sum_nbr h[nbr], stored fp16 -------------
    const uint2* hh = (const uint2*)Ain;
#pragma unroll 1
    for (int rr = 0; rr < 8; rr++) {
        int r = wid * 8 + rr;
        int node = m0 + r;
        float4 acc = f4zero();
        if (node < M) {
            acc = h2f4(hh[node * 32 + lane]);
            int s0 = g_offs[node], s1 = g_offs[node + 1];
            int j = s0;
            for (; j + 15 < s1; j += 16) GATHER16(hh, j);
            for (; j < s1; j++) {
                float4 u = h2f4(hh[g_perm[j] * 32 + lane]);
                acc.x += u.x; acc.y += u.y; acc.z += u.z; acc.w += u.w;
            }
        }
        *(uint2*)(sa + r * AST + lane * 4) = f42h(acc);
    }
    if (mode == 2 && tid < 64)
        sbat[tid] = (m0 + tid < M) ? g_batch[m0 + tid] : -1;
    __syncthreads();

    // ---- tensor phase: 2-product fp16 (A exact fp16, W = hi + lo) ---------------
    wmma::fragment<wmma::accumulator, 16, 16, 16, float> facc[4];
#pragma unroll
    for (int r = 0; r < 4; r++) wmma::fill_fragment(facc[r], 0.f);

    const __half* Bh = g_Wfh + widx * 16384 + wid * 16;
    const __half* Bl = g_Wfl + widx * 16384 + wid * 16;

#pragma unroll 1
    for (int k = 0; k < 8; k++) {
        wmma::fragment<wmma::matrix_b, 16, 16, 16, __half, wmma::row_major> bh, bl;
        wmma::load_matrix_sync(bh, Bh + (k * 16) * 128, 128);
        wmma::load_matrix_sync(bl, Bl + (k * 16) * 128, 128);
#pragma unroll
        for (int r = 0; r < 4; r++) {
            wmma::fragment<wmma::matrix_a, 16, 16, 16, __half, wmma::row_major> a;
            wmma::load_matrix_sync(a, sa + (r * 16) * AST + k * 16, AST);
            wmma::mma_sync(facc[r], a, bh, facc[r]);
            wmma::mma_sync(facc[r], a, bl, facc[r]);
        }
    }

    // ---- chunked epilogue (2 x 32 rows; reuses the A plane) ---------------------
    float* cs = (float*)sm;
#pragma unroll 1
    for (int chunk = 0; chunk < 2; chunk++) {
        __syncthreads();
#pragma unroll
        for (int r = 0; r < 2; r++)
            wmma::store_matrix_sync(cs + (r * 16) * CST + wid * 16,
                                    facc[2 * chunk + r], CST, wmma::mem_row_major);
        __syncthreads();

        if (mode == 2) {
            // pool: 2 threads per column, 16 sorted rows each
            int c = tid & 127;
            int base = chunk * 32 + (tid >> 7) * 16;   // global-tile row base
            int lbase = (tid >> 7) * 16;               // local row base in chunk
            float b = bias[c];
            float acc = 0.f;
            int cur = sbat[base];
            for (int r = 0; r < 16; r++) {
                int g = sbat[base + r];
                if (g < 0) break;
                if (g != cur) {
                    atomicAdd(&g_pool[cur * HH + c], acc);
                    acc = 0.f; cur = g;
                }
                acc += fmaxf(cs[(lbase + r) * CST + c] + b, 0.f);
            }
            if (cur >= 0 && acc != 0.f) atomicAdd(&g_pool[cur * HH + c], acc);
        } else {
            const float4* b4p = (const float4*)bias;
#pragma unroll
            for (int i = 0; i < 4; i++) {
                int idx = tid + i * 256;       // 1024 slots = 32 rows x 32 quads
                int r = idx >> 5, q = idx & 31;
                int grow = m0 + chunk * 32 + r;
                if (grow < M) {
                    float4 o = *(float4*)(cs + r * CST + q * 4);
                    float4 bb = b4p[q];
                    o.x = fmaxf(o.x + bb.x, 0.f); o.y = fmaxf(o.y + bb.y, 0.f);
                    o.z = fmaxf(o.z + bb.z, 0.f); o.w = fmaxf(o.w + bb.w, 0.f);
                    ((uint2*)Cout)[grow * 32 + q] = f42h(o);
                }
            }
        }
    }
}

// ---------------- GCN aggregation (half in, half out; per-edge dinv) -------------
__global__ void k_gcn_agg(const __half* __restrict__ h, const float* __restrict__ b0,
                          __half* __restrict__ out) {
    int node = blockIdx.x * 8 + (threadIdx.x >> 5);
    if (node >= NN) return;
    int lane = threadIdx.x & 31;
    const uint2* hh = (const uint2*)h;

    float di = g_dinv[node];
    float4 hs = h2f4(hh[node * 32 + lane]);
    float4 acc = make_float4(di * hs.x, di * hs.y, di * hs.z, di * hs.w);
    int s0 = g_offs[node], s1 = g_offs[node + 1];
    int j = s0;
    for (; j + 15 < s1; j += 16) {
        int ix[16];
#pragma unroll
        for (int t = 0; t < 16; t++) ix[t] = g_perm[j + t];
        float cc[16];
        uint2 rr[16];
#pragma unroll
        for (int t = 0; t < 16; t++) { cc[t] = g_dinv[ix[t]]; rr[t] = hh[ix[t] * 32 + lane]; }
#pragma unroll
        for (int t = 0; t < 16; t++) {
            float4 u = h2f4(rr[t]);
            acc.x = fmaf(cc[t], u.x, acc.x);
            acc.y = fmaf(cc[t], u.y, acc.y);
            acc.z = fmaf(cc[t], u.z, acc.z);
            acc.w = fmaf(cc[t], u.w, acc.w);
        }
    }
    for (; j < s1; j++) {
        int n0 = g_perm[j];
        float c0 = g_dinv[n0];
        float4 u = h2f4(hh[n0 * 32 + lane]);
        acc.x = fmaf(c0, u.x, acc.x); acc.y = fmaf(c0, u.y, acc.y);
        acc.z = fmaf(c0, u.z, acc.z); acc.w = fmaf(c0, u.w, acc.w);
    }
    float4 b = ((const float4*)b0)[lane];
    float4 o;
    o.x = fmaxf(fmaf(di, acc.x, b.x), 0.f);
    o.y = fmaxf(fmaf(di, acc.y, b.y), 0.f);
    o.z = fmaxf(fmaf(di, acc.z, b.z), 0.f);
    o.w = fmaxf(fmaf(di, acc.w, b.w), 0.f);
    ((uint2*)out)[node * 32 + lane] = f42h(o);
}

// ---------------- fused head MLP: out[g] = Wh2^T relu(Wh1^T mean_g + bh1) + bh2 --
__global__ void k_head(const float* __restrict__ Wh1, const float* __restrict__ bh1,
                       const float* __restrict__ Wh2, const float* __restrict__ bh2,
                       float* __restrict__ out) {
    __shared__ float sp[HH];
    __shared__ float shid[NHID];
    int g = blockIdx.x, c = threadIdx.x;
    float inv = 1.f / fmaxf(g_cnt[g], 1.f);
    if (c < HH) sp[c] = g_pool[g * HH + c] * inv;
    __syncthreads();

    float acc = bh1[c];
#pragma unroll 8
    for (int k = 0; k < HH; k++)
        acc = fmaf(sp[k], __ldg(&Wh1[k * NHID + c]), acc);
    shid[c] = fmaxf(acc, 0.f);
    __syncthreads();

    if (c < NOUT) {
        float acc2 = bh2[c];
#pragma unroll 8
        for (int k = 0; k < NHID; k++)
            acc2 = fmaf(shid[k], __ldg(&Wh2[k * NOUT + c]), acc2);
        out[g * NOUT + c] = acc2;
    }
}

// ---------------- launch ----------------
extern "C" void kernel_launch(void* const* d_in, const int* in_sizes, int n_in,
                              void* d_out, int out_size) {
    (void)in_sizes; (void)n_in; (void)out_size;
    const float* x   = (const float*)d_in[0];
    const void*  ei  = d_in[1];
    const void*  bat = d_in[2];
    const float* W0  = (const float*)d_in[3];
    const float* b0  = (const float*)d_in[4];
    const float* Wg1 = (const float*)d_in[5];
    const float* bg1 = (const float*)d_in[6];
    const float* Wg2 = (const float*)d_in[7];
    const float* bg2 = (const float*)d_in[8];
    const float* Wh1 = (const float*)d_in[9];
    const float* bh1 = (const float*)d_in[10];
    const float* Wh2 = (const float*)d_in[11];
    const float* bh2 = (const float*)d_in[12];
    float* out = (float*)d_out;

    __half *h0, *h1, *h2;
    cudaGetSymbolAddress((void**)&h0, g_h0);
    cudaGetSymbolAddress((void**)&h1, g_h1);
    cudaGetSymbolAddress((void**)&h2, g_h2);

    static cudaStream_t s2 = nullptr;
    static cudaEvent_t evA = nullptr, evB = nullptr;
    if (!s2) {
        cudaStreamCreateWithFlags(&s2, cudaStreamNonBlocking);
        cudaEventCreateWithFlags(&evA, cudaEventDisableTiming);
        cudaEventCreateWithFlags(&evB, cudaEventDisableTiming);
    }

    const int TB = 256;
    int mma_blocks = (NN + 63) / 64;     // 782
    int agg_blocks = (NN + 7) / 8;

    // setup (zero + detect + weight images)
    k_setup<<<388, TB>>>((const unsigned int*)ei, W0, Wg1, Wg2);

    // fork: GEMM1 (x @ W0 -> h0 fp16) on s2, concurrent with the CSR build chain
    cudaEventRecord(evA, 0);
    cudaStreamWaitEvent(s2, evA, 0);
    k_wmma0<<<mma_blocks, 256, 0, s2>>>(x, h0, NN);
    cudaEventRecord(evB, s2);

    // main: CSR build
    k_count<<<(EE + TB - 1) / TB, TB>>>(ei, bat);
    k_scanA<<<49, 1024>>>();
    k_scanB<<<1, 1>>>();
    k_scanC<<<49, 1024>>>();
    k_fill<<<(EE + TB - 1) / TB, TB>>>(ei);

    // join: gcn_agg needs both h0 (GEMM1) and the CSR
    cudaStreamWaitEvent(0, evB, 0);
    k_gcn_agg<<<agg_blocks, 256>>>(h0, b0, h1);
    // GIN layer 1 (fused half gather + 2-product fp16 WMMA -> h2 fp16)
    k_wmma_gin<<<mma_blocks, 256>>>(h1, 0, bg1, h2, NN, 1);
    // GIN layer 2 (fused half gather + 2-product fp16 WMMA; epilogue pools)
    k_wmma_gin<<<mma_blocks, 256>>>(h2, 1, bg2, nullptr, NN, 2);
    // fused head MLP
    k_head<<<GG, NHID>>>(Wh1, bh1, Wh2, bh2, out);
}